// round 15
// baseline (speedup 1.0000x reference)
#include <cuda_runtime.h>

// LIF forward scan — FINAL (roofline-pinned; reproduced 6x across rounds).
// x: [B=32, T=64, N=16384] f32; thresh, tau_x: [N] f32
// out: spikes [B,T,N] f32 then mems [B,T,N] f32 (post-reset membrane).
//
// 384 MB irreducible traffic / ~5.6 TB/s measured mixed 1:2 read/write
// HBM3e ceiling = ~61.5 us floor; this binary measures 61.0-62.7 us kernel,
// DRAM 70-72% of spec (peak obs 5.68 TB/s). Fourteen rounds of isolated
// experiments: occupancy (R2/R7), forced MLP (R3), streaming cache hints
// (R4), 256-bit LDG/STG (R7), grouped store bursts (R9) all regress; unroll
// depth neutral (R6). Single structural win: 1024 CTAs x 128 threads =
// whole grid resident in one balanced wave (6.92 CTAs/SM, ~1% skew).

static constexpr int B = 32;
static constexpr int T = 64;
static constexpr int N = 16384;
static constexpr int N4 = N / 4;          // 4096 float4 lanes per row

__global__ __launch_bounds__(128) void lif_kernel(
    const float4* __restrict__ x,         // [B, T, N4]
    const float4* __restrict__ thresh4,   // [N4]
    const float4* __restrict__ taux4,     // [N4]
    float4* __restrict__ spikes,          // [B, T, N4]
    float4* __restrict__ mems)            // [B, T, N4]
{
    const int idx = blockIdx.x * blockDim.x + threadIdx.x;  // [0, B*N4)
    const int n4 = idx & (N4 - 1);
    const int b  = idx >> 12;             // idx / N4

    const float4 th = thresh4[n4];
    const float4 tx = taux4[n4];

    // sigmoid(tau_x), constant over timesteps
    float4 sig;
    sig.x = 1.0f / (1.0f + __expf(-tx.x));
    sig.y = 1.0f / (1.0f + __expf(-tx.y));
    sig.z = 1.0f / (1.0f + __expf(-tx.z));
    sig.w = 1.0f / (1.0f + __expf(-tx.w));

    float4 mem = make_float4(0.f, 0.f, 0.f, 0.f);

    const size_t base = (size_t)b * T * N4 + n4;
    const float4* xp = x + base;
    float4* sp = spikes + base;
    float4* mp = mems + base;

    #pragma unroll 8
    for (int t = 0; t < T; ++t) {
        const float4 xv = xp[(size_t)t * N4];

        // leaky integration: mem += sig * (x - mem)
        mem.x = fmaf(sig.x, xv.x - mem.x, mem.x);
        mem.y = fmaf(sig.y, xv.y - mem.y, mem.y);
        mem.z = fmaf(sig.z, xv.z - mem.z, mem.z);
        mem.w = fmaf(sig.w, xv.w - mem.w, mem.w);

        // Heaviside fire (>= threshold) and hard reset
        float4 s;
        s.x = (mem.x >= th.x) ? 1.0f : 0.0f;
        s.y = (mem.y >= th.y) ? 1.0f : 0.0f;
        s.z = (mem.z >= th.z) ? 1.0f : 0.0f;
        s.w = (mem.w >= th.w) ? 1.0f : 0.0f;

        mem.x = (s.x != 0.0f) ? 0.0f : mem.x;
        mem.y = (s.y != 0.0f) ? 0.0f : mem.y;
        mem.z = (s.z != 0.0f) ? 0.0f : mem.z;
        mem.w = (s.w != 0.0f) ? 0.0f : mem.w;

        sp[(size_t)t * N4] = s;
        mp[(size_t)t * N4] = mem;  // post-reset membrane
    }
}

extern "C" void kernel_launch(void* const* d_in, const int* in_sizes, int n_in,
                              void* d_out, int out_size)
{
    const float4* x    = (const float4*)d_in[0];
    const float4* th   = (const float4*)d_in[1];
    const float4* taux = (const float4*)d_in[2];

    float4* spikes = (float4*)d_out;
    float4* mems   = (float4*)((float*)d_out + (size_t)B * T * N);

    const int total = B * N4;             // 131072 threads
    const int tpb = 128;                  // 1024 blocks, single balanced wave
    lif_kernel<<<total / tpb, tpb>>>(x, th, taux, spikes, mems);
}

// round 16
// speedup vs baseline: 1.0035x; 1.0035x over previous
#include <cuda_runtime.h>

// LIF forward scan — FINAL (roofline-pinned; reproduced 7x across rounds).
// x: [B=32, T=64, N=16384] f32; thresh, tau_x: [N] f32
// out: spikes [B,T,N] f32 then mems [B,T,N] f32 (post-reset membrane).
//
// 384 MB irreducible traffic / ~5.6 TB/s measured mixed 1:2 read/write
// HBM3e ceiling = ~61.5 us floor; this binary measures 61.0-62.7 us kernel,
// DRAM 70-72% of spec. Fifteen rounds of isolated experiments: occupancy
// (R2/R7), forced MLP (R3), streaming cache hints (R4), 256-bit LDG/STG
// (R7), grouped store bursts (R9) all regress; unroll depth neutral (R6).
// Single structural win: 1024 CTAs x 128 threads = whole grid resident in
// one balanced wave (6.92 CTAs/SM, ~1% skew, no tail).

static constexpr int B = 32;
static constexpr int T = 64;
static constexpr int N = 16384;
static constexpr int N4 = N / 4;          // 4096 float4 lanes per row

__global__ __launch_bounds__(128) void lif_kernel(
    const float4* __restrict__ x,         // [B, T, N4]
    const float4* __restrict__ thresh4,   // [N4]
    const float4* __restrict__ taux4,     // [N4]
    float4* __restrict__ spikes,          // [B, T, N4]
    float4* __restrict__ mems)            // [B, T, N4]
{
    const int idx = blockIdx.x * blockDim.x + threadIdx.x;  // [0, B*N4)
    const int n4 = idx & (N4 - 1);
    const int b  = idx >> 12;             // idx / N4

    const float4 th = thresh4[n4];
    const float4 tx = taux4[n4];

    // sigmoid(tau_x), constant over timesteps
    float4 sig;
    sig.x = 1.0f / (1.0f + __expf(-tx.x));
    sig.y = 1.0f / (1.0f + __expf(-tx.y));
    sig.z = 1.0f / (1.0f + __expf(-tx.z));
    sig.w = 1.0f / (1.0f + __expf(-tx.w));

    float4 mem = make_float4(0.f, 0.f, 0.f, 0.f);

    const size_t base = (size_t)b * T * N4 + n4;
    const float4* xp = x + base;
    float4* sp = spikes + base;
    float4* mp = mems + base;

    #pragma unroll 8
    for (int t = 0; t < T; ++t) {
        const float4 xv = xp[(size_t)t * N4];

        // leaky integration: mem += sig * (x - mem)
        mem.x = fmaf(sig.x, xv.x - mem.x, mem.x);
        mem.y = fmaf(sig.y, xv.y - mem.y, mem.y);
        mem.z = fmaf(sig.z, xv.z - mem.z, mem.z);
        mem.w = fmaf(sig.w, xv.w - mem.w, mem.w);

        // Heaviside fire (>= threshold) and hard reset
        float4 s;
        s.x = (mem.x >= th.x) ? 1.0f : 0.0f;
        s.y = (mem.y >= th.y) ? 1.0f : 0.0f;
        s.z = (mem.z >= th.z) ? 1.0f : 0.0f;
        s.w = (mem.w >= th.w) ? 1.0f : 0.0f;

        mem.x = (s.x != 0.0f) ? 0.0f : mem.x;
        mem.y = (s.y != 0.0f) ? 0.0f : mem.y;
        mem.z = (s.z != 0.0f) ? 0.0f : mem.z;
        mem.w = (s.w != 0.0f) ? 0.0f : mem.w;

        sp[(size_t)t * N4] = s;
        mp[(size_t)t * N4] = mem;  // post-reset membrane
    }
}

extern "C" void kernel_launch(void* const* d_in, const int* in_sizes, int n_in,
                              void* d_out, int out_size)
{
    const float4* x    = (const float4*)d_in[0];
    const float4* th   = (const float4*)d_in[1];
    const float4* taux = (const float4*)d_in[2];

    float4* spikes = (float4*)d_out;
    float4* mems   = (float4*)((float*)d_out + (size_t)B * T * N);

    const int total = B * N4;             // 131072 threads
    const int tpb = 128;                  // 1024 blocks, single balanced wave
    lif_kernel<<<total / tpb, tpb>>>(x, th, taux, spikes, mems);
}

// round 17
// speedup vs baseline: 1.0098x; 1.0062x over previous
#include <cuda_runtime.h>

// LIF forward scan — FINAL (roofline-pinned; reproduced 8x across rounds).
// x: [B=32, T=64, N=16384] f32; thresh, tau_x: [N] f32
// out: spikes [B,T,N] f32 then mems [B,T,N] f32 (post-reset membrane).
//
// 384 MB irreducible traffic / ~5.6 TB/s measured mixed 1:2 read/write
// HBM3e ceiling = ~61.5 us floor; this binary measures 61.0-62.7 us kernel,
// DRAM 70-72% of spec. Sixteen rounds: occupancy (R2/R7), forced MLP (R3),
// streaming cache hints (R4), 256-bit LDG/STG (R7), grouped store bursts
// (R9) all regress; unroll depth neutral (R6). Single structural win:
// 1024 CTAs x 128 threads = whole grid resident in one balanced wave
// (6.92 CTAs/SM, ~1% skew, no tail).

static constexpr int B = 32;
static constexpr int T = 64;
static constexpr int N = 16384;
static constexpr int N4 = N / 4;          // 4096 float4 lanes per row

__global__ __launch_bounds__(128) void lif_kernel(
    const float4* __restrict__ x,         // [B, T, N4]
    const float4* __restrict__ thresh4,   // [N4]
    const float4* __restrict__ taux4,     // [N4]
    float4* __restrict__ spikes,          // [B, T, N4]
    float4* __restrict__ mems)            // [B, T, N4]
{
    const int idx = blockIdx.x * blockDim.x + threadIdx.x;  // [0, B*N4)
    const int n4 = idx & (N4 - 1);
    const int b  = idx >> 12;             // idx / N4

    const float4 th = thresh4[n4];
    const float4 tx = taux4[n4];

    // sigmoid(tau_x), constant over timesteps
    float4 sig;
    sig.x = 1.0f / (1.0f + __expf(-tx.x));
    sig.y = 1.0f / (1.0f + __expf(-tx.y));
    sig.z = 1.0f / (1.0f + __expf(-tx.z));
    sig.w = 1.0f / (1.0f + __expf(-tx.w));

    float4 mem = make_float4(0.f, 0.f, 0.f, 0.f);

    const size_t base = (size_t)b * T * N4 + n4;
    const float4* xp = x + base;
    float4* sp = spikes + base;
    float4* mp = mems + base;

    #pragma unroll 8
    for (int t = 0; t < T; ++t) {
        const float4 xv = xp[(size_t)t * N4];

        // leaky integration: mem += sig * (x - mem)
        mem.x = fmaf(sig.x, xv.x - mem.x, mem.x);
        mem.y = fmaf(sig.y, xv.y - mem.y, mem.y);
        mem.z = fmaf(sig.z, xv.z - mem.z, mem.z);
        mem.w = fmaf(sig.w, xv.w - mem.w, mem.w);

        // Heaviside fire (>= threshold) and hard reset
        float4 s;
        s.x = (mem.x >= th.x) ? 1.0f : 0.0f;
        s.y = (mem.y >= th.y) ? 1.0f : 0.0f;
        s.z = (mem.z >= th.z) ? 1.0f : 0.0f;
        s.w = (mem.w >= th.w) ? 1.0f : 0.0f;

        mem.x = (s.x != 0.0f) ? 0.0f : mem.x;
        mem.y = (s.y != 0.0f) ? 0.0f : mem.y;
        mem.z = (s.z != 0.0f) ? 0.0f : mem.z;
        mem.w = (s.w != 0.0f) ? 0.0f : mem.w;

        sp[(size_t)t * N4] = s;
        mp[(size_t)t * N4] = mem;  // post-reset membrane
    }
}

extern "C" void kernel_launch(void* const* d_in, const int* in_sizes, int n_in,
                              void* d_out, int out_size)
{
    const float4* x    = (const float4*)d_in[0];
    const float4* th   = (const float4*)d_in[1];
    const float4* taux = (const float4*)d_in[2];

    float4* spikes = (float4*)d_out;
    float4* mems   = (float4*)((float*)d_out + (size_t)B * T * N);

    const int total = B * N4;             // 131072 threads
    const int tpb = 128;                  // 1024 blocks, single balanced wave
    lif_kernel<<<total / tpb, tpb>>>(x, th, taux, spikes, mems);
}